// round 2
// baseline (speedup 1.0000x reference)
#include <cuda_runtime.h>
#include <math.h>

// Problem constants
#define NROWS 65536
#define DIN   512
#define HID   2048
#define DOUT  512

// e3nn path normalization
#define S_IN  0.04419417382415922f   // 1/sqrt(512)
#define S_H   0.02209708691207961f   // 1/sqrt(2048)

// Tiling
#define BM 128
#define BN 128
#define BK 16
#define TM 8
#define TN 8
#define NTHREADS 256

// Scratch for hidden activations (allowed: static __device__ arrays)
__device__ float g_H1[(size_t)NROWS * HID];  // cos branch, 512 MB
__device__ float g_H2[(size_t)NROWS * HID];  // sigmoid branch, 512 MB

// ---------------------------------------------------------------------------
// Stage 1: H1 = cos(X @ W1 * s_in + bias), H2 = sigmoid(X @ W3 * s_in)
// Dual-branch GEMM: X tile loaded once, accumulated against both W1 and W3.
// Grid: (HID/BN, NROWS/BM), 256 threads, 8x8 microtile per branch.
// ---------------------------------------------------------------------------
__global__ __launch_bounds__(NTHREADS, 1)
void hidden_kernel(const float* __restrict__ x,
                   const float* __restrict__ W1,
                   const float* __restrict__ bias,
                   const float* __restrict__ W3)
{
    __shared__ float As[BK][BM + 4];   // X tile, transposed, padded
    __shared__ float B1s[BK][BN];      // W1 tile
    __shared__ float B2s[BK][BN];      // W3 tile

    const int htile = blockIdx.x;
    const int ntile = blockIdx.y;
    const int tid = threadIdx.x;
    const int ty = tid >> 4;          // 0..15
    const int tx = tid & 15;          // 0..15

    const float* xg  = x  + (size_t)ntile * BM * DIN;
    const float* w1g = W1 + (size_t)htile * BN;
    const float* w3g = W3 + (size_t)htile * BN;

    float acc1[TM][TN];
    float acc2[TM][TN];
#pragma unroll
    for (int i = 0; i < TM; i++)
#pragma unroll
        for (int j = 0; j < TN; j++) { acc1[i][j] = 0.f; acc2[i][j] = 0.f; }

    float4 xr[2], w1r[2], w3r[2];

    // --- tile loaders (global -> regs) ---
    auto loadX = [&](int k0) {
#pragma unroll
        for (int i = 0; i < 2; i++) {
            int s = tid * 2 + i;              // 0..511 slots
            int row = s >> 2;                 // 0..127
            int c = (s & 3) * 4;              // 0..12
            xr[i] = *(const float4*)&xg[(size_t)row * DIN + k0 + c];
        }
    };
    auto loadW = [&](int k0) {
#pragma unroll
        for (int i = 0; i < 2; i++) {
            int s = tid * 2 + i;              // 0..511
            int row = s >> 5;                 // 0..15 (k within tile)
            int c = (s & 31) * 4;             // 0..124
            w1r[i] = *(const float4*)&w1g[(size_t)(k0 + row) * HID + c];
            w3r[i] = *(const float4*)&w3g[(size_t)(k0 + row) * HID + c];
        }
    };
    // --- regs -> smem ---
    auto storeTiles = [&]() {
#pragma unroll
        for (int i = 0; i < 2; i++) {
            int s = tid * 2 + i;
            int row = s >> 2;
            int c = (s & 3) * 4;
            As[c + 0][row] = xr[i].x;
            As[c + 1][row] = xr[i].y;
            As[c + 2][row] = xr[i].z;
            As[c + 3][row] = xr[i].w;
            int wrow = s >> 5;
            int wc = (s & 31) * 4;
            *(float4*)&B1s[wrow][wc] = w1r[i];
            *(float4*)&B2s[wrow][wc] = w3r[i];
        }
    };

    loadX(0); loadW(0);
    storeTiles();
    __syncthreads();

    for (int kt = 0; kt < DIN / BK; kt++) {
        const int knext = (kt + 1) * BK;
        if (knext < DIN) { loadX(knext); loadW(knext); }

#pragma unroll
        for (int kk = 0; kk < BK; kk++) {
            float a[TM], b1[TN], b2[TN];
            *(float4*)&a[0]  = *(const float4*)&As[kk][ty * TM];
            *(float4*)&a[4]  = *(const float4*)&As[kk][ty * TM + 4];
            *(float4*)&b1[0] = *(const float4*)&B1s[kk][tx * TN];
            *(float4*)&b1[4] = *(const float4*)&B1s[kk][tx * TN + 4];
            *(float4*)&b2[0] = *(const float4*)&B2s[kk][tx * TN];
            *(float4*)&b2[4] = *(const float4*)&B2s[kk][tx * TN + 4];
#pragma unroll
            for (int i = 0; i < TM; i++)
#pragma unroll
                for (int j = 0; j < TN; j++) {
                    acc1[i][j] = fmaf(a[i], b1[j], acc1[i][j]);
                    acc2[i][j] = fmaf(a[i], b2[j], acc2[i][j]);
                }
        }
        __syncthreads();
        if (knext < DIN) {
            storeTiles();
            __syncthreads();
        }
    }

    // Epilogue: activations + store
    const int col0 = htile * BN + tx * TN;
    float bcol[TN];
#pragma unroll
    for (int j = 0; j < TN; j++) bcol[j] = bias[col0 + j];

#pragma unroll
    for (int i = 0; i < TM; i++) {
        const int row = ntile * BM + ty * TM + i;
        float h1v[TN], h2v[TN];
#pragma unroll
        for (int j = 0; j < TN; j++) {
            h1v[j] = cosf(acc1[i][j] * S_IN + bcol[j]);
            float z = acc2[i][j] * S_IN;
            h2v[j] = 1.f / (1.f + expf(-z));
        }
        float* p1 = &g_H1[(size_t)row * HID + col0];
        float* p2 = &g_H2[(size_t)row * HID + col0];
        *(float4*)&p1[0] = *(float4*)&h1v[0];
        *(float4*)&p1[4] = *(float4*)&h1v[4];
        *(float4*)&p2[0] = *(float4*)&h2v[0];
        *(float4*)&p2[4] = *(float4*)&h2v[4];
    }
}

// ---------------------------------------------------------------------------
// Stage 2: out = (H1 @ W2 * s_h) * (H2 @ W4 * s_h)
// Dual GEMM over K=2048, fused final elementwise product.
// Grid: (DOUT/BN, NROWS/BM)
// ---------------------------------------------------------------------------
__global__ __launch_bounds__(NTHREADS, 1)
void output_kernel(const float* __restrict__ W2,
                   const float* __restrict__ W4,
                   float* __restrict__ out)
{
    __shared__ float A1s[BK][BM + 4];
    __shared__ float A2s[BK][BM + 4];
    __shared__ float B1s[BK][BN];
    __shared__ float B2s[BK][BN];

    const int ctile = blockIdx.x;     // output-column tile (0..3)
    const int ntile = blockIdx.y;
    const int tid = threadIdx.x;
    const int ty = tid >> 4;
    const int tx = tid & 15;

    const float* a1g = g_H1 + (size_t)ntile * BM * HID;
    const float* a2g = g_H2 + (size_t)ntile * BM * HID;
    const float* w2g = W2 + (size_t)ctile * BN;
    const float* w4g = W4 + (size_t)ctile * BN;

    float acc1[TM][TN];
    float acc2[TM][TN];
#pragma unroll
    for (int i = 0; i < TM; i++)
#pragma unroll
        for (int j = 0; j < TN; j++) { acc1[i][j] = 0.f; acc2[i][j] = 0.f; }

    float4 a1r[2], a2r[2], w2r[2], w4r[2];

    auto loadA = [&](int k0) {
#pragma unroll
        for (int i = 0; i < 2; i++) {
            int s = tid * 2 + i;
            int row = s >> 2;
            int c = (s & 3) * 4;
            a1r[i] = *(const float4*)&a1g[(size_t)row * HID + k0 + c];
            a2r[i] = *(const float4*)&a2g[(size_t)row * HID + k0 + c];
        }
    };
    auto loadW = [&](int k0) {
#pragma unroll
        for (int i = 0; i < 2; i++) {
            int s = tid * 2 + i;
            int row = s >> 5;
            int c = (s & 31) * 4;
            w2r[i] = *(const float4*)&w2g[(size_t)(k0 + row) * DOUT + c];
            w4r[i] = *(const float4*)&w4g[(size_t)(k0 + row) * DOUT + c];
        }
    };
    auto storeTiles = [&]() {
#pragma unroll
        for (int i = 0; i < 2; i++) {
            int s = tid * 2 + i;
            int row = s >> 2;
            int c = (s & 3) * 4;
            A1s[c + 0][row] = a1r[i].x;  A2s[c + 0][row] = a2r[i].x;
            A1s[c + 1][row] = a1r[i].y;  A2s[c + 1][row] = a2r[i].y;
            A1s[c + 2][row] = a1r[i].z;  A2s[c + 2][row] = a2r[i].z;
            A1s[c + 3][row] = a1r[i].w;  A2s[c + 3][row] = a2r[i].w;
            int wrow = s >> 5;
            int wc = (s & 31) * 4;
            *(float4*)&B1s[wrow][wc] = w2r[i];
            *(float4*)&B2s[wrow][wc] = w4r[i];
        }
    };

    loadA(0); loadW(0);
    storeTiles();
    __syncthreads();

    for (int kt = 0; kt < HID / BK; kt++) {
        const int knext = (kt + 1) * BK;
        if (knext < HID) { loadA(knext); loadW(knext); }

#pragma unroll
        for (int kk = 0; kk < BK; kk++) {
            float a1[TM], a2[TM], b1[TN], b2[TN];
            *(float4*)&a1[0] = *(const float4*)&A1s[kk][ty * TM];
            *(float4*)&a1[4] = *(const float4*)&A1s[kk][ty * TM + 4];
            *(float4*)&a2[0] = *(const float4*)&A2s[kk][ty * TM];
            *(float4*)&a2[4] = *(const float4*)&A2s[kk][ty * TM + 4];
            *(float4*)&b1[0] = *(const float4*)&B1s[kk][tx * TN];
            *(float4*)&b1[4] = *(const float4*)&B1s[kk][tx * TN + 4];
            *(float4*)&b2[0] = *(const float4*)&B2s[kk][tx * TN];
            *(float4*)&b2[4] = *(const float4*)&B2s[kk][tx * TN + 4];
#pragma unroll
            for (int i = 0; i < TM; i++)
#pragma unroll
                for (int j = 0; j < TN; j++) {
                    acc1[i][j] = fmaf(a1[i], b1[j], acc1[i][j]);
                    acc2[i][j] = fmaf(a2[i], b2[j], acc2[i][j]);
                }
        }
        __syncthreads();
        if (knext < HID) {
            storeTiles();
            __syncthreads();
        }
    }

    const int col0 = ctile * BN + tx * TN;
#pragma unroll
    for (int i = 0; i < TM; i++) {
        const int row = ntile * BM + ty * TM + i;
        float ov[TN];
#pragma unroll
        for (int j = 0; j < TN; j++)
            ov[j] = (acc1[i][j] * S_H) * (acc2[i][j] * S_H);
        float* p = &out[(size_t)row * DOUT + col0];
        *(float4*)&p[0] = *(float4*)&ov[0];
        *(float4*)&p[4] = *(float4*)&ov[4];
    }
}

// ---------------------------------------------------------------------------
// Inputs (metadata order): x, W_rff1, bias, W_rff2, W_sig1, W_sig2
// ---------------------------------------------------------------------------
extern "C" void kernel_launch(void* const* d_in, const int* in_sizes, int n_in,
                              void* d_out, int out_size)
{
    (void)in_sizes; (void)n_in; (void)out_size;
    const float* x     = (const float*)d_in[0];
    const float* W1    = (const float*)d_in[1];
    const float* bias  = (const float*)d_in[2];
    const float* W2    = (const float*)d_in[3];
    const float* W3    = (const float*)d_in[4];
    const float* W4    = (const float*)d_in[5];
    float* out = (float*)d_out;

    dim3 g1(HID / BN, NROWS / BM);     // (16, 512)
    hidden_kernel<<<g1, NTHREADS>>>(x, W1, bias, W3);

    dim3 g2(DOUT / BN, NROWS / BM);    // (4, 512)
    output_kernel<<<g2, NTHREADS>>>(W2, W4, out);
}

// round 4
// speedup vs baseline: 2.4543x; 2.4543x over previous
#include <cuda_runtime.h>
#include <cuda_bf16.h>
#include <cstdint>
#include <math.h>

// ---------------- problem constants ----------------
#define NROWS 65536
#define DIN   512
#define HID   2048
#define DOUT  512
#define S_IN  0.04419417382415922f    // 1/sqrt(512)
#define S_H2  4.8828125e-4f           // (1/sqrt(2048))^2

// ---------------- scratch (static __device__, allowed) ----------------
__device__ __align__(256) __nv_bfloat16 g_Xh [(size_t)NROWS * DIN];
__device__ __align__(256) __nv_bfloat16 g_Xl [(size_t)NROWS * DIN];
__device__ __align__(256) __nv_bfloat16 g_W1th[(size_t)HID * DIN];   // [H][DIN]
__device__ __align__(256) __nv_bfloat16 g_W1tl[(size_t)HID * DIN];
__device__ __align__(256) __nv_bfloat16 g_W3th[(size_t)HID * DIN];
__device__ __align__(256) __nv_bfloat16 g_W3tl[(size_t)HID * DIN];
__device__ __align__(256) __nv_bfloat16 g_W2th[(size_t)DOUT * HID];  // [DOUT][H]
__device__ __align__(256) __nv_bfloat16 g_W2tl[(size_t)DOUT * HID];
__device__ __align__(256) __nv_bfloat16 g_W4th[(size_t)DOUT * HID];
__device__ __align__(256) __nv_bfloat16 g_W4tl[(size_t)DOUT * HID];
__device__ __align__(256) __nv_bfloat16 g_H1h[(size_t)NROWS * HID];
__device__ __align__(256) __nv_bfloat16 g_H1l[(size_t)NROWS * HID];
__device__ __align__(256) __nv_bfloat16 g_H2h[(size_t)NROWS * HID];
__device__ __align__(256) __nv_bfloat16 g_H2l[(size_t)NROWS * HID];

// ---------------- helpers ----------------
__device__ __forceinline__ uint32_t smem_u32(const void* p) {
    uint32_t a;
    asm("{ .reg .u64 t; cvta.to.shared.u64 t, %1; cvt.u32.u64 %0, t; }" : "=r"(a) : "l"(p));
    return a;
}
__device__ __forceinline__ void cp16(uint32_t d, const void* s) {
    asm volatile("cp.async.cg.shared.global [%0], [%1], 16;" :: "r"(d), "l"(s));
}
#define CP_COMMIT() asm volatile("cp.async.commit_group;" ::: "memory")
#define CP_WAIT1()  asm volatile("cp.async.wait_group 1;" ::: "memory")

__device__ __forceinline__ void ldsm4(uint32_t (&r)[4], uint32_t addr) {
    asm volatile("ldmatrix.sync.aligned.m8n8.x4.shared.b16 {%0,%1,%2,%3}, [%4];"
                 : "=r"(r[0]), "=r"(r[1]), "=r"(r[2]), "=r"(r[3]) : "r"(addr));
}
__device__ __forceinline__ void mma16816(float (&d)[4], const uint32_t (&a)[4],
                                         uint32_t b0, uint32_t b1) {
    asm volatile(
        "mma.sync.aligned.m16n8k16.row.col.f32.bf16.bf16.f32 "
        "{%0,%1,%2,%3}, {%4,%5,%6,%7}, {%8,%9}, {%0,%1,%2,%3};"
        : "+f"(d[0]), "+f"(d[1]), "+f"(d[2]), "+f"(d[3])
        : "r"(a[0]), "r"(a[1]), "r"(a[2]), "r"(a[3]), "r"(b0), "r"(b1));
}

// SW64 swizzle for 64B-wide tile rows ([128][32] bf16 = 8KB tiles)
#define SWZ64(o) ((o) ^ (((o) >> 3) & 0x30))
#define TILE_B 8192

__device__ __forceinline__ uint32_t pack_bf2(__nv_bfloat16 a, __nv_bfloat16 b) {
    __nv_bfloat162 v(a, b);
    return *(uint32_t*)&v;
}

// ---------------- prep kernels ----------------
__global__ void split_x_kernel(const float* __restrict__ x) {
    size_t i = (size_t)blockIdx.x * 256 + threadIdx.x;          // float4 index
    float4 v = ((const float4*)x)[i];
    __nv_bfloat16 h[4], l[4];
    h[0] = __float2bfloat16_rn(v.x); l[0] = __float2bfloat16_rn(v.x - __bfloat162float(h[0]));
    h[1] = __float2bfloat16_rn(v.y); l[1] = __float2bfloat16_rn(v.y - __bfloat162float(h[1]));
    h[2] = __float2bfloat16_rn(v.z); l[2] = __float2bfloat16_rn(v.z - __bfloat162float(h[2]));
    h[3] = __float2bfloat16_rn(v.w); l[3] = __float2bfloat16_rn(v.w - __bfloat162float(h[3]));
    ((uint2*)g_Xh)[i] = *(uint2*)h;
    ((uint2*)g_Xl)[i] = *(uint2*)l;
}

// transpose in[K][N] -> out[N][K] with hi/lo split; block (32,8), grid (K/32, N/32)
__global__ void tsplit_kernel(const float* __restrict__ in, int which, int K, int N) {
    __nv_bfloat16 *oh, *ol;
    if (which == 0)      { oh = g_W1th; ol = g_W1tl; }
    else if (which == 1) { oh = g_W3th; ol = g_W3tl; }
    else if (which == 2) { oh = g_W2th; ol = g_W2tl; }
    else                 { oh = g_W4th; ol = g_W4tl; }
    __shared__ float t[32][33];
    int k0 = blockIdx.x * 32, n0 = blockIdx.y * 32;
    int tx = threadIdx.x, ty = threadIdx.y;
#pragma unroll
    for (int i = 0; i < 4; i++) {
        int k = ty + i * 8;
        t[k][tx] = in[(size_t)(k0 + k) * N + n0 + tx];
    }
    __syncthreads();
#pragma unroll
    for (int i = 0; i < 4; i++) {
        int n = ty + i * 8;
        float v = t[tx][n];
        __nv_bfloat16 h = __float2bfloat16_rn(v);
        oh[(size_t)(n0 + n) * K + k0 + tx] = h;
        ol[(size_t)(n0 + n) * K + k0 + tx] = __float2bfloat16_rn(v - __bfloat162float(h));
    }
}

// ---------------- stage 1: dual GEMM (K=512) + activations ----------------
// grid (16, 512): x = H-col tile, y = row tile; 256 threads; tiles [128][32] bf16
#define S1_SMEM (2 * 6 * TILE_B)   // 98304
__global__ __launch_bounds__(256, 1) void stage1_kernel(const float* __restrict__ bias) {
    extern __shared__ char smem[];
    const uint32_t sb = smem_u32(smem);
    const int tid = threadIdx.x, wid = tid >> 5, lane = tid & 31;
    const int warp_m = wid >> 1, warp_n = wid & 1;
    const int m0 = blockIdx.y * 128, n0 = blockIdx.x * 128;

    const int r_lane = (lane & 7) + ((lane >> 3) & 1) * 8;
    const int halfb  = ((lane >> 4) & 1) * 16;

    const __nv_bfloat16* srcs[6] = {
        g_Xh   + (size_t)m0 * DIN, g_Xl   + (size_t)m0 * DIN,
        g_W1th + (size_t)n0 * DIN, g_W1tl + (size_t)n0 * DIN,
        g_W3th + (size_t)n0 * DIN, g_W3tl + (size_t)n0 * DIN };

    float acc1[2][8][4], acc2[2][8][4];
#pragma unroll
    for (int m = 0; m < 2; m++)
#pragma unroll
        for (int nf = 0; nf < 8; nf++)
#pragma unroll
            for (int e = 0; e < 4; e++) { acc1[m][nf][e] = 0.f; acc2[m][nf][e] = 0.f; }

    auto load_chunk = [&](int c, int buf) {
        int k0 = c * 32;
#pragma unroll
        for (int t = 0; t < 6; t++) {
            uint32_t tb = sb + (uint32_t)(buf * 6 + t) * TILE_B;
            const __nv_bfloat16* base = srcs[t];
#pragma unroll
            for (int i = 0; i < 2; i++) {
                int s = tid + i * 256;
                int row = s >> 2, v = s & 3;
                cp16(tb + SWZ64(row * 64 + v * 16), base + (size_t)row * DIN + k0 + v * 8);
            }
        }
    };

    load_chunk(0, 0); CP_COMMIT();
    const int NCH = DIN / 32;   // 16
    for (int c = 0; c < NCH; c++) {
        const int cur = c & 1;
        if (c + 1 < NCH) load_chunk(c + 1, (c + 1) & 1);
        CP_COMMIT();
        CP_WAIT1();
        __syncthreads();

        const uint32_t tb0 = sb + (uint32_t)(cur * 6) * TILE_B;
#pragma unroll
        for (int ks = 0; ks < 2; ks++) {
            const int kb = ks * 32;
            uint32_t Ah[2][4], Al[2][4];
#pragma unroll
            for (int m = 0; m < 2; m++) {
                uint32_t off = SWZ64((warp_m * 32 + m * 16 + r_lane) * 64 + kb + halfb);
                ldsm4(Ah[m], tb0 + off);
                ldsm4(Al[m], tb0 + TILE_B + off);
            }
#pragma unroll
            for (int p = 0; p < 4; p++) {
                uint32_t offB = SWZ64((warp_n * 64 + p * 16 + r_lane) * 64 + kb + halfb);
                uint32_t b1h[4], b1l[4], b2h[4], b2l[4];
                ldsm4(b1h, tb0 + 2 * TILE_B + offB);
                ldsm4(b1l, tb0 + 3 * TILE_B + offB);
                ldsm4(b2h, tb0 + 4 * TILE_B + offB);
                ldsm4(b2l, tb0 + 5 * TILE_B + offB);
#pragma unroll
                for (int e = 0; e < 2; e++) {
                    const int nf = p * 2 + e;
#pragma unroll
                    for (int m = 0; m < 2; m++) {
                        mma16816(acc1[m][nf], Ah[m], b1h[e], b1h[2 + e]);
                        mma16816(acc1[m][nf], Ah[m], b1l[e], b1l[2 + e]);
                        mma16816(acc1[m][nf], Al[m], b1h[e], b1h[2 + e]);
                        mma16816(acc2[m][nf], Ah[m], b2h[e], b2h[2 + e]);
                        mma16816(acc2[m][nf], Ah[m], b2l[e], b2l[2 + e]);
                        mma16816(acc2[m][nf], Al[m], b2h[e], b2h[2 + e]);
                    }
                }
            }
        }
        __syncthreads();
    }

    // epilogue: activations, hi/lo split, store
    const int g = lane >> 2, t4 = lane & 3;
#pragma unroll
    for (int m = 0; m < 2; m++) {
#pragma unroll
        for (int nf = 0; nf < 8; nf++) {
            const int col = n0 + warp_n * 64 + nf * 8 + t4 * 2;
            const float b0 = __ldg(bias + col), b1v = __ldg(bias + col + 1);
#pragma unroll
            for (int h = 0; h < 2; h++) {
                const int row = m0 + warp_m * 32 + m * 16 + g + h * 8;
                float s1a = acc1[m][nf][h * 2 + 0] * S_IN + b0;
                float s1b = acc1[m][nf][h * 2 + 1] * S_IN + b1v;
                float h1a = __cosf(s1a), h1b = __cosf(s1b);
                float z0 = acc2[m][nf][h * 2 + 0] * S_IN;
                float z1 = acc2[m][nf][h * 2 + 1] * S_IN;
                float h2a = 1.f / (1.f + __expf(-z0));
                float h2b = 1.f / (1.f + __expf(-z1));

                __nv_bfloat16 a1h = __float2bfloat16_rn(h1a);
                __nv_bfloat16 b1h = __float2bfloat16_rn(h1b);
                __nv_bfloat16 a1l = __float2bfloat16_rn(h1a - __bfloat162float(a1h));
                __nv_bfloat16 b1l = __float2bfloat16_rn(h1b - __bfloat162float(b1h));
                __nv_bfloat16 a2h = __float2bfloat16_rn(h2a);
                __nv_bfloat16 b2h = __float2bfloat16_rn(h2b);
                __nv_bfloat16 a2l = __float2bfloat16_rn(h2a - __bfloat162float(a2h));
                __nv_bfloat16 b2l = __float2bfloat16_rn(h2b - __bfloat162float(b2h));

                size_t go = (size_t)row * HID + col;
                *(uint32_t*)(g_H1h + go) = pack_bf2(a1h, b1h);
                *(uint32_t*)(g_H1l + go) = pack_bf2(a1l, b1l);
                *(uint32_t*)(g_H2h + go) = pack_bf2(a2h, b2h);
                *(uint32_t*)(g_H2l + go) = pack_bf2(a2l, b2l);
            }
        }
    }
}

// ---------------- stage 2: fused dual GEMM (K=2048) + product ----------------
// grid (4, 512): x = DOUT col tile, y = row tile
#define S2_SMEM (2 * 8 * TILE_B)   // 131072
__global__ __launch_bounds__(256, 1) void stage2_kernel(float* __restrict__ out) {
    extern __shared__ char smem[];
    const uint32_t sb = smem_u32(smem);
    const int tid = threadIdx.x, wid = tid >> 5, lane = tid & 31;
    const int warp_m = wid >> 1, warp_n = wid & 1;
    const int m0 = blockIdx.y * 128, c0 = blockIdx.x * 128;

    const int r_lane = (lane & 7) + ((lane >> 3) & 1) * 8;
    const int halfb  = ((lane >> 4) & 1) * 16;

    const __nv_bfloat16* srcs[8] = {
        g_H1h  + (size_t)m0 * HID, g_H1l  + (size_t)m0 * HID,
        g_H2h  + (size_t)m0 * HID, g_H2l  + (size_t)m0 * HID,
        g_W2th + (size_t)c0 * HID, g_W2tl + (size_t)c0 * HID,
        g_W4th + (size_t)c0 * HID, g_W4tl + (size_t)c0 * HID };

    float acc1[2][8][4], acc2[2][8][4];
#pragma unroll
    for (int m = 0; m < 2; m++)
#pragma unroll
        for (int nf = 0; nf < 8; nf++)
#pragma unroll
            for (int e = 0; e < 4; e++) { acc1[m][nf][e] = 0.f; acc2[m][nf][e] = 0.f; }

    auto load_chunk = [&](int c, int buf) {
        int k0 = c * 32;
#pragma unroll
        for (int t = 0; t < 8; t++) {
            uint32_t tb = sb + (uint32_t)(buf * 8 + t) * TILE_B;
            const __nv_bfloat16* base = srcs[t];
#pragma unroll
            for (int i = 0; i < 2; i++) {
                int s = tid + i * 256;
                int row = s >> 2, v = s & 3;
                cp16(tb + SWZ64(row * 64 + v * 16), base + (size_t)row * HID + k0 + v * 8);
            }
        }
    };

    load_chunk(0, 0); CP_COMMIT();
    const int NCH = HID / 32;   // 64
    for (int c = 0; c < NCH; c++) {
        const int cur = c & 1;
        if (c + 1 < NCH) load_chunk(c + 1, (c + 1) & 1);
        CP_COMMIT();
        CP_WAIT1();
        __syncthreads();

        const uint32_t tb0 = sb + (uint32_t)(cur * 8) * TILE_B;
#pragma unroll
        for (int ks = 0; ks < 2; ks++) {
            const int kb = ks * 32;
            uint32_t A1h[2][4], A1l[2][4], A2h[2][4], A2l[2][4];
#pragma unroll
            for (int m = 0; m < 2; m++) {
                uint32_t off = SWZ64((warp_m * 32 + m * 16 + r_lane) * 64 + kb + halfb);
                ldsm4(A1h[m], tb0 + off);
                ldsm4(A1l[m], tb0 + TILE_B + off);
                ldsm4(A2h[m], tb0 + 2 * TILE_B + off);
                ldsm4(A2l[m], tb0 + 3 * TILE_B + off);
            }
#pragma unroll
            for (int p = 0; p < 4; p++) {
                uint32_t offB = SWZ64((warp_n * 64 + p * 16 + r_lane) * 64 + kb + halfb);
                uint32_t b1h[4], b1l[4], b2h[4], b2l[4];
                ldsm4(b1h, tb0 + 4 * TILE_B + offB);
                ldsm4(b1l, tb0 + 5 * TILE_B + offB);
                ldsm4(b2h, tb0 + 6 * TILE_B + offB);
                ldsm4(b2l, tb0 + 7 * TILE_B + offB);
#pragma unroll
                for (int e = 0; e < 2; e++) {
                    const int nf = p * 2 + e;
#pragma unroll
                    for (int m = 0; m < 2; m++) {
                        mma16816(acc1[m][nf], A1h[m], b1h[e], b1h[2 + e]);
                        mma16816(acc1[m][nf], A1h[m], b1l[e], b1l[2 + e]);
                        mma16816(acc1[m][nf], A1l[m], b1h[e], b1h[2 + e]);
                        mma16816(acc2[m][nf], A2h[m], b2h[e], b2h[2 + e]);
                        mma16816(acc2[m][nf], A2h[m], b2l[e], b2l[2 + e]);
                        mma16816(acc2[m][nf], A2l[m], b2h[e], b2h[2 + e]);
                    }
                }
            }
        }
        __syncthreads();
    }

    // epilogue: out = acc1*acc2*S_H2 (fp32)
    const int g = lane >> 2, t4 = lane & 3;
#pragma unroll
    for (int m = 0; m < 2; m++) {
#pragma unroll
        for (int nf = 0; nf < 8; nf++) {
            const int col = c0 + warp_n * 64 + nf * 8 + t4 * 2;
#pragma unroll
            for (int h = 0; h < 2; h++) {
                const int row = m0 + warp_m * 32 + m * 16 + g + h * 8;
                float2 o;
                o.x = acc1[m][nf][h * 2 + 0] * acc2[m][nf][h * 2 + 0] * S_H2;
                o.y = acc1[m][nf][h * 2 + 1] * acc2[m][nf][h * 2 + 1] * S_H2;
                *(float2*)(out + (size_t)row * DOUT + col) = o;
            }
        }
    }
}

// ---------------- launch ----------------
// Inputs (metadata order): x, W_rff1, bias, W_rff2, W_sig1, W_sig2
extern "C" void kernel_launch(void* const* d_in, const int* in_sizes, int n_in,
                              void* d_out, int out_size)
{
    (void)in_sizes; (void)n_in; (void)out_size;
    const float* x    = (const float*)d_in[0];
    const float* W1   = (const float*)d_in[1];
    const float* bias = (const float*)d_in[2];
    const float* W2   = (const float*)d_in[3];
    const float* W3   = (const float*)d_in[4];
    const float* W4   = (const float*)d_in[5];
    float* out = (float*)d_out;

    cudaFuncSetAttribute(stage1_kernel, cudaFuncAttributeMaxDynamicSharedMemorySize, S1_SMEM);
    cudaFuncSetAttribute(stage2_kernel, cudaFuncAttributeMaxDynamicSharedMemorySize, S2_SMEM);

    split_x_kernel<<<(NROWS * DIN / 4) / 256, 256>>>(x);
    // W1, W3: [DIN][HID] -> [HID][DIN]
    tsplit_kernel<<<dim3(DIN / 32, HID / 32), dim3(32, 8)>>>(W1, 0, DIN, HID);
    tsplit_kernel<<<dim3(DIN / 32, HID / 32), dim3(32, 8)>>>(W3, 1, DIN, HID);
    // W2, W4: [HID][DOUT] -> [DOUT][HID]
    tsplit_kernel<<<dim3(HID / 32, DOUT / 32), dim3(32, 8)>>>(W2, 2, HID, DOUT);
    tsplit_kernel<<<dim3(HID / 32, DOUT / 32), dim3(32, 8)>>>(W4, 3, HID, DOUT);

    stage1_kernel<<<dim3(HID / 128, NROWS / 128), 256, S1_SMEM>>>(bias);
    stage2_kernel<<<dim3(DOUT / 128, NROWS / 128), 256, S2_SMEM>>>(out);
}